// round 14
// baseline (speedup 1.0000x reference)
#include <cuda_runtime.h>
#include <stdint.h>

// ---------------------------------------------------------------------------
// ExtractGraph: maxpool2x2 -> +uniform noise -> diagonal-stencil adjacency
// (transposed) -> bernoulli(0.5) dropout. Output float32.
// RNG = JAX threefry2x32, partitionable scheme:
//   split(key)[i]      = both output words of threefry(key, (0, i))
//   random_bits(32)[t] = o0 ^ o1 of threefry(key, (hi(t), lo(t)))
// R14: dropout cipher moved OUT of the stencil kernel entirely. Graph writes
// adj as 1.0/0.0 and appends adj-true flat indices (~1.5% = ~60K) to a global
// list (warp-aggregated atomics). A tiny fixup kernel ciphers ONLY the listed
// elements and zeroes the dropped ones. Bit-exact; warp-level cipher cost
// eliminated from the 4M-element pass.
// ---------------------------------------------------------------------------

#define PM 2048
#define PN 2048

static __device__ float    g_dnT[(size_t)PM * PN];   // d_noised TRANSPOSED: g_dnT[j][i]
static __device__ unsigned g_min_u = 0xFFFFFFFFu;    // static init; atomics idempotent
static __device__ unsigned g_max_u = 0u;
static __device__ unsigned g_list[(size_t)PM * PN];  // adj-true flat indices
static __device__ unsigned g_cnt;                    // list length (memset per launch)

__device__ __forceinline__ uint32_t rotl32(uint32_t x, int d) {
    return __funnelshift_l(x, x, d);     // single SHF
}

// Threefry-2x32, 20 rounds, exactly as in jax/_src/prng.py.
__device__ __forceinline__ void tf2x32(uint32_t k0, uint32_t k1,
                                       uint32_t c0, uint32_t c1,
                                       uint32_t& o0, uint32_t& o1) {
    uint32_t ks2 = k0 ^ k1 ^ 0x1BD11BDAu;
    uint32_t x0 = c0 + k0;
    uint32_t x1 = c1 + k1;
#define TFR(R) { x0 += x1; x1 = rotl32(x1, R); x1 ^= x0; }
    TFR(13) TFR(15) TFR(26) TFR(6)
    x0 += k1;  x1 += ks2 + 1u;
    TFR(17) TFR(29) TFR(16) TFR(24)
    x0 += ks2; x1 += k0 + 2u;
    TFR(13) TFR(15) TFR(26) TFR(6)
    x0 += k0;  x1 += k1 + 3u;
    TFR(17) TFR(29) TFR(16) TFR(24)
    x0 += k1;  x1 += ks2 + 4u;
    TFR(13) TFR(15) TFR(26) TFR(6)
    x0 += ks2; x1 += k0 + 5u;
#undef TFR
    o0 = x0; o1 = x1;
}

__device__ __forceinline__ uint32_t tf_bits32(uint32_t k0, uint32_t k1,
                                              uint32_t c0, uint32_t c1) {
    uint32_t o0, o1;
    tf2x32(k0, k1, c0, c1, o0, o1);
    return o0 ^ o1;
}

// JAX uniform(0,1) float32 from 32 random bits.
__device__ __forceinline__ float u01(uint32_t b) {
    return __uint_as_float((b >> 9) | 0x3f800000u) - 1.0f;
}

// Order-preserving float<->uint mapping (no NaNs in input).
__device__ __forceinline__ unsigned f2sortable(float f) {
    unsigned u = __float_as_uint(f);
    return (u & 0x80000000u) ? ~u : (u | 0x80000000u);
}
__device__ __forceinline__ float sortable2f(unsigned u) {
    unsigned b = (u & 0x80000000u) ? (u ^ 0x80000000u) : ~u;
    return __uint_as_float(b);
}

// Kernel A (R13 proven): maxpool 2x2 + threefry noise. float4 loads, fma-pipe
// min/max accumulation, conflict-free float4 transposed drain.
__global__ void __launch_bounds__(256) pool_noise_kernel(
    const float* __restrict__ dc, uint32_t kn0, uint32_t kn1) {
    __shared__ float s[64][33];          // s[col_local][row_local]
    const int tx = threadIdx.x, ty = threadIdx.y;
    const int j0 = blockIdx.x * 64;
    const int i0 = blockIdx.y * 32;
    const int jj = 2 * tx;

    float fmn = __uint_as_float(0x7f800000u);    // +inf
    float fmx = __uint_as_float(0xff800000u);    // -inf

#pragma unroll
    for (int k = 0; k < 4; ++k) {
        const int i = i0 + ty + 8 * k;
        const float4* row0 = reinterpret_cast<const float4*>(dc + ((uint32_t)(2 * i) << 12));
        const float4* row1 = reinterpret_cast<const float4*>(dc + ((uint32_t)(2 * i + 1) << 12));
        const float4 a = __ldg(&row0[(j0 >> 1) + tx]);
        const float4 b = __ldg(&row1[(j0 >> 1) + tx]);
        const float p0 = fmaxf(fmaxf(a.x, a.y), fmaxf(b.x, b.y));
        const float p1 = fmaxf(fmaxf(a.z, a.w), fmaxf(b.z, b.w));

        fmn = fminf(fmn, fminf(p0, p1));
        fmx = fmaxf(fmx, fmaxf(p0, p1));

        const uint32_t t0 = ((uint32_t)i << 11) + (uint32_t)(j0 + jj);
        const uint32_t bn0 = tf_bits32(kn0, kn1, 0u, t0);
        const uint32_t bn1 = tf_bits32(kn0, kn1, 0u, t0 + 1u);

        const int l = ty + 8 * k;
        s[jj][l]     = p0 + u01(bn0);
        s[jj + 1][l] = p1 + u01(bn1);
    }
    __syncthreads();

    {
        const int t = ty * 32 + tx;
        const int c = t >> 2;
        const int rg = (t & 3) * 8;
        const float4 v0 = make_float4(s[c][rg],     s[c][rg + 1],
                                      s[c][rg + 2], s[c][rg + 3]);
        const float4 v1 = make_float4(s[c][rg + 4], s[c][rg + 5],
                                      s[c][rg + 6], s[c][rg + 7]);
        float* dst = &g_dnT[((uint32_t)(j0 + c) << 11) + (uint32_t)(i0 + rg)];
        *reinterpret_cast<float4*>(dst)     = v0;
        *reinterpret_cast<float4*>(dst + 4) = v1;
    }

    unsigned lmin = __reduce_min_sync(0xffffffffu, f2sortable(fmn));
    unsigned lmax = __reduce_max_sync(0xffffffffu, f2sortable(fmx));
    __shared__ unsigned rmin[8], rmax[8];
    if (tx == 0) { rmin[ty] = lmin; rmax[ty] = lmax; }
    __syncthreads();
    if (ty == 0 && tx == 0) {
        unsigned m0 = rmin[0], m1 = rmax[0];
#pragma unroll
        for (int w = 1; w < 8; ++w) { m0 = min(m0, rmin[w]); m1 = max(m1, rmax[w]); }
        atomicMin(&g_min_u, m0);
        atomicMax(&g_max_u, m1);
    }
}

// Kernel B: stencil only. Writes adj as 1.0/0.0 and appends adj-true flat
// indices to g_list via warp-aggregated atomics. NO cipher here.
__global__ void __launch_bounds__(256) graph_kernel(float* __restrict__ out) {
    const int c0 = (blockIdx.x * 32 + threadIdx.x) * 4;
    const int r  = blockIdx.y * 8 + threadIdx.y;

    float thr;
    if ((threadIdx.x & 31) == 0)
        thr = (sortable2f(g_max_u) - sortable2f(g_min_u)) * (1.0f / 2048.0f);
    thr = __shfl_sync(0xffffffffu, thr, 0);

    const uint32_t rowb = (uint32_t)r << 11;

    const bool interior = (blockIdx.x != 0) & (blockIdx.x != gridDim.x - 1) &
                          (blockIdx.y != 0) & (blockIdx.y != gridDim.y - 1);

    bool adj[4];
    if (interior) {
        const float4 ctr = *reinterpret_cast<const float4*>(&g_dnT[rowb + c0]);
        const float* up_row = &g_dnT[rowb - PM];
        const float* dn_row = &g_dnT[rowb + PM];
        const float4 u4 = *reinterpret_cast<const float4*>(up_row + c0);
        const float4 d4 = *reinterpret_cast<const float4*>(dn_row + c0);
        float up[6], dw[6];
        up[1] = u4.x; up[2] = u4.y; up[3] = u4.z; up[4] = u4.w;
        dw[1] = d4.x; dw[2] = d4.y; dw[3] = d4.z; dw[4] = d4.w;
        up[0] = up_row[c0 - 1]; up[5] = up_row[c0 + 4];
        dw[0] = dn_row[c0 - 1]; dw[5] = dn_row[c0 + 4];

        const float cx[4] = {ctr.x, ctr.y, ctr.z, ctr.w};
#pragma unroll
        for (int e = 0; e < 4; ++e) {
            const float x = cx[e];
            const float m = fminf(fminf(fabsf(up[e] - x), fabsf(up[e + 2] - x)),
                                  fminf(fabsf(dw[e] - x), fabsf(dw[e + 2] - x)));
            adj[e] = (m <= thr);
        }
    } else {
        const bool rm = (r >= 1), rp = (r <= PM - 2);
        const float4 ctr = *reinterpret_cast<const float4*>(&g_dnT[rowb + c0]);
        const float* up_row = &g_dnT[(uint32_t)(rm ? r - 1 : r) << 11];
        const float* dn_row = &g_dnT[(uint32_t)(rp ? r + 1 : r) << 11];
        const int cl = (c0 > 0) ? c0 - 1 : 0;
        const int cr = (c0 + 4 < PN) ? c0 + 4 : PN - 1;

        float up[6], dw[6];
        const float4 u4 = *reinterpret_cast<const float4*>(up_row + c0);
        const float4 d4 = *reinterpret_cast<const float4*>(dn_row + c0);
        up[1] = u4.x; up[2] = u4.y; up[3] = u4.z; up[4] = u4.w;
        dw[1] = d4.x; dw[2] = d4.y; dw[3] = d4.z; dw[4] = d4.w;
        up[0] = up_row[cl]; up[5] = up_row[cr];
        dw[0] = dn_row[cl]; dw[5] = dn_row[cr];

        const float cx[4] = {ctr.x, ctr.y, ctr.z, ctr.w};
#pragma unroll
        for (int e = 0; e < 4; ++e) {
            const int c = c0 + e;
            const bool cm = (c >= 1), cp = (c <= PN - 2);
            const float x = cx[e];
            bool a = false;
            a |= (cm && rm)             && (fabsf(up[e]     - x) <= thr);
            a |= (cm && cp && rm && rp) && (fabsf(up[e + 2] - x) <= thr);
            a |= (cm && rp)             && (fabsf(dw[e]     - x) <= thr);
            a |= (cp && rp)             && (fabsf(dw[e + 2] - x) <= thr);
            adj[e] = a;
        }
    }

    // store adj as float (branchless), append adj-true indices to list
    *reinterpret_cast<float4*>(&out[rowb + c0]) =
        make_float4(adj[0] ? 1.0f : 0.0f, adj[1] ? 1.0f : 0.0f,
                    adj[2] ? 1.0f : 0.0f, adj[3] ? 1.0f : 0.0f);

    const unsigned lane_lt = (1u << (threadIdx.x & 31)) - 1u;
#pragma unroll
    for (int e = 0; e < 4; ++e) {
        const unsigned mk = __ballot_sync(0xffffffffu, adj[e]);
        if (mk) {
            const int leader = __ffs(mk) - 1;
            unsigned base = 0;
            if ((int)(threadIdx.x & 31) == leader)
                base = atomicAdd(&g_cnt, (unsigned)__popc(mk));
            base = __shfl_sync(0xffffffffu, base, leader);
            if (adj[e])
                g_list[base + __popc(mk & lane_lt)] = rowb + (uint32_t)(c0 + e);
        }
    }
}

// Kernel C: dense dropout cipher over the listed (~60K) elements only.
__global__ void __launch_bounds__(256) drop_fixup_kernel(
    float* __restrict__ out, uint32_t kd0, uint32_t kd1) {
    const unsigned n = g_cnt;
    for (unsigned idx = blockIdx.x * 256u + threadIdx.x; idx < n;
         idx += gridDim.x * 256u) {
        const uint32_t t = g_list[idx];
        const uint32_t bd = tf_bits32(kd0, kd1, 0u, t);
        if (bd & 0x80000000u) out[t] = 0.0f;   // u01(bd) >= 0.5 -> dropped
    }
}

extern "C" void kernel_launch(void* const* d_in, const int* in_sizes, int n_in,
                              void* d_out, int out_size) {
    (void)in_sizes; (void)n_in; (void)out_size;
    const float* dc = (const float*)d_in[0];
    float* out = (float*)d_out;

    // host-side threefry for the key split
    auto rotl_h = [](uint32_t x, int d) { return (x << d) | (x >> (32 - d)); };
    auto tf_h = [&](uint32_t k0, uint32_t k1, uint32_t c0, uint32_t c1,
                    uint32_t& o0, uint32_t& o1) {
        uint32_t ks2 = k0 ^ k1 ^ 0x1BD11BDAu;
        uint32_t x0 = c0 + k0, x1 = c1 + k1;
        const int ra[4] = {13, 15, 26, 6}, rb[4] = {17, 29, 16, 24};
        for (int g = 0; g < 5; ++g) {
            const int* rr = (g & 1) ? rb : ra;
            for (int q = 0; q < 4; ++q) { x0 += x1; x1 = rotl_h(x1, rr[q]); x1 ^= x0; }
            switch (g) {
                case 0: x0 += k1;  x1 += ks2 + 1u; break;
                case 1: x0 += ks2; x1 += k0 + 2u;  break;
                case 2: x0 += k0;  x1 += k1 + 3u;  break;
                case 3: x0 += k1;  x1 += ks2 + 4u; break;
                case 4: x0 += ks2; x1 += k0 + 5u;  break;
            }
        }
        o0 = x0; o1 = x1;
    };

    uint32_t kn0, kn1, kd0, kd1;
    tf_h(0u, 1u, 0u, 0u, kn0, kn1);   // k_noise
    tf_h(0u, 1u, 0u, 1u, kd0, kd1);   // k_drop

    // reset the append counter (deterministic across graph replays)
    void* pcnt = nullptr;
    cudaGetSymbolAddress(&pcnt, g_cnt);
    cudaMemsetAsync(pcnt, 0x00, 4);

    pool_noise_kernel<<<dim3(32, 64), dim3(32, 8)>>>(dc, kn0, kn1);
    graph_kernel<<<dim3(16, 256), dim3(32, 8)>>>(out);
    drop_fixup_kernel<<<296, 256>>>(out, kd0, kd1);
}

// round 15
// speedup vs baseline: 1.9269x; 1.9269x over previous
#include <cuda_runtime.h>
#include <stdint.h>

// ---------------------------------------------------------------------------
// ExtractGraph: maxpool2x2 -> +uniform noise -> diagonal-stencil adjacency
// (transposed) -> bernoulli(0.5) dropout. Output float32.
// RNG = JAX threefry2x32, partitionable scheme:
//   split(key)[i]      = both output words of threefry(key, (0, i))
//   random_bits(32)[t] = o0 ^ o1 of threefry(key, (hi(t), lo(t)))
// R15 = R13 (proven 29.4us) + BLOCK-LOCAL compaction of the lazy dropout
// cipher: survivors (~15/block of 1024) are appended to an smem list via one
// shared atomic per warp, then ciphered densely after __syncthreads. No
// global list, no extra kernel (R14's global-atomic mistake reverted).
// ---------------------------------------------------------------------------

#define PM 2048
#define PN 2048

static __device__ float    g_dnT[(size_t)PM * PN];   // d_noised TRANSPOSED: g_dnT[j][i]
static __device__ unsigned g_min_u = 0xFFFFFFFFu;    // static init; atomics idempotent
static __device__ unsigned g_max_u = 0u;

__device__ __forceinline__ uint32_t rotl32(uint32_t x, int d) {
    return __funnelshift_l(x, x, d);     // single SHF
}

// Threefry-2x32, 20 rounds, exactly as in jax/_src/prng.py.
__device__ __forceinline__ void tf2x32(uint32_t k0, uint32_t k1,
                                       uint32_t c0, uint32_t c1,
                                       uint32_t& o0, uint32_t& o1) {
    uint32_t ks2 = k0 ^ k1 ^ 0x1BD11BDAu;
    uint32_t x0 = c0 + k0;
    uint32_t x1 = c1 + k1;
#define TFR(R) { x0 += x1; x1 = rotl32(x1, R); x1 ^= x0; }
    TFR(13) TFR(15) TFR(26) TFR(6)
    x0 += k1;  x1 += ks2 + 1u;
    TFR(17) TFR(29) TFR(16) TFR(24)
    x0 += ks2; x1 += k0 + 2u;
    TFR(13) TFR(15) TFR(26) TFR(6)
    x0 += k0;  x1 += k1 + 3u;
    TFR(17) TFR(29) TFR(16) TFR(24)
    x0 += k1;  x1 += ks2 + 4u;
    TFR(13) TFR(15) TFR(26) TFR(6)
    x0 += ks2; x1 += k0 + 5u;
#undef TFR
    o0 = x0; o1 = x1;
}

__device__ __forceinline__ uint32_t tf_bits32(uint32_t k0, uint32_t k1,
                                              uint32_t c0, uint32_t c1) {
    uint32_t o0, o1;
    tf2x32(k0, k1, c0, c1, o0, o1);
    return o0 ^ o1;
}

// JAX uniform(0,1) float32 from 32 random bits.
__device__ __forceinline__ float u01(uint32_t b) {
    return __uint_as_float((b >> 9) | 0x3f800000u) - 1.0f;
}

// Order-preserving float<->uint mapping (no NaNs in input).
__device__ __forceinline__ unsigned f2sortable(float f) {
    unsigned u = __float_as_uint(f);
    return (u & 0x80000000u) ? ~u : (u | 0x80000000u);
}
__device__ __forceinline__ float sortable2f(unsigned u) {
    unsigned b = (u & 0x80000000u) ? (u ^ 0x80000000u) : ~u;
    return __uint_as_float(b);
}

// Kernel A (R13 proven): maxpool 2x2 + threefry noise. float4 loads, fma-pipe
// min/max accumulation, conflict-free float4 transposed drain.
__global__ void __launch_bounds__(256) pool_noise_kernel(
    const float* __restrict__ dc, uint32_t kn0, uint32_t kn1) {
    __shared__ float s[64][33];          // s[col_local][row_local]
    const int tx = threadIdx.x, ty = threadIdx.y;
    const int j0 = blockIdx.x * 64;
    const int i0 = blockIdx.y * 32;
    const int jj = 2 * tx;

    float fmn = __uint_as_float(0x7f800000u);    // +inf
    float fmx = __uint_as_float(0xff800000u);    // -inf

#pragma unroll
    for (int k = 0; k < 4; ++k) {
        const int i = i0 + ty + 8 * k;
        const float4* row0 = reinterpret_cast<const float4*>(dc + ((uint32_t)(2 * i) << 12));
        const float4* row1 = reinterpret_cast<const float4*>(dc + ((uint32_t)(2 * i + 1) << 12));
        const float4 a = __ldg(&row0[(j0 >> 1) + tx]);
        const float4 b = __ldg(&row1[(j0 >> 1) + tx]);
        const float p0 = fmaxf(fmaxf(a.x, a.y), fmaxf(b.x, b.y));
        const float p1 = fmaxf(fmaxf(a.z, a.w), fmaxf(b.z, b.w));

        fmn = fminf(fmn, fminf(p0, p1));
        fmx = fmaxf(fmx, fmaxf(p0, p1));

        const uint32_t t0 = ((uint32_t)i << 11) + (uint32_t)(j0 + jj);
        const uint32_t bn0 = tf_bits32(kn0, kn1, 0u, t0);
        const uint32_t bn1 = tf_bits32(kn0, kn1, 0u, t0 + 1u);

        const int l = ty + 8 * k;
        s[jj][l]     = p0 + u01(bn0);
        s[jj + 1][l] = p1 + u01(bn1);
    }
    __syncthreads();

    {
        const int t = ty * 32 + tx;
        const int c = t >> 2;
        const int rg = (t & 3) * 8;
        const float4 v0 = make_float4(s[c][rg],     s[c][rg + 1],
                                      s[c][rg + 2], s[c][rg + 3]);
        const float4 v1 = make_float4(s[c][rg + 4], s[c][rg + 5],
                                      s[c][rg + 6], s[c][rg + 7]);
        float* dst = &g_dnT[((uint32_t)(j0 + c) << 11) + (uint32_t)(i0 + rg)];
        *reinterpret_cast<float4*>(dst)     = v0;
        *reinterpret_cast<float4*>(dst + 4) = v1;
    }

    unsigned lmin = __reduce_min_sync(0xffffffffu, f2sortable(fmn));
    unsigned lmax = __reduce_max_sync(0xffffffffu, f2sortable(fmx));
    __shared__ unsigned rmin[8], rmax[8];
    if (tx == 0) { rmin[ty] = lmin; rmax[ty] = lmax; }
    __syncthreads();
    if (ty == 0 && tx == 0) {
        unsigned m0 = rmin[0], m1 = rmax[0];
#pragma unroll
        for (int w = 1; w < 8; ++w) { m0 = min(m0, rmin[w]); m1 = max(m1, rmax[w]); }
        atomicMin(&g_min_u, m0);
        atomicMax(&g_max_u, m1);
    }
}

// Kernel B: stencil (4 elems/thread, float4 I/O, interior/rim split), writes
// adj as 1.0/0.0. Survivor indices compacted into an smem list (one shared
// atomic per warp), then ciphered densely by the whole block.
__global__ void __launch_bounds__(256) graph_kernel(
    float* __restrict__ out, uint32_t kd0, uint32_t kd1) {
    __shared__ unsigned sh_cnt;
    __shared__ uint32_t s_list[1024];

    const int tx = threadIdx.x;                 // 0..31 (blockDim.x == 32)
    const int tid = threadIdx.y * 32 + tx;
    if (tid == 0) sh_cnt = 0u;

    const int c0 = (blockIdx.x * 32 + tx) * 4;
    const int r  = blockIdx.y * 8 + threadIdx.y;

    float thr;
    if (tx == 0)
        thr = (sortable2f(g_max_u) - sortable2f(g_min_u)) * (1.0f / 2048.0f);
    thr = __shfl_sync(0xffffffffu, thr, 0);

    const uint32_t rowb = (uint32_t)r << 11;

    const bool interior = (blockIdx.x != 0) & (blockIdx.x != gridDim.x - 1) &
                          (blockIdx.y != 0) & (blockIdx.y != gridDim.y - 1);

    bool adj[4];
    if (interior) {
        const float4 ctr = *reinterpret_cast<const float4*>(&g_dnT[rowb + c0]);
        const float* up_row = &g_dnT[rowb - PM];
        const float* dn_row = &g_dnT[rowb + PM];
        const float4 u4 = *reinterpret_cast<const float4*>(up_row + c0);
        const float4 d4 = *reinterpret_cast<const float4*>(dn_row + c0);
        float up[6], dw[6];
        up[1] = u4.x; up[2] = u4.y; up[3] = u4.z; up[4] = u4.w;
        dw[1] = d4.x; dw[2] = d4.y; dw[3] = d4.z; dw[4] = d4.w;
        up[0] = up_row[c0 - 1]; up[5] = up_row[c0 + 4];
        dw[0] = dn_row[c0 - 1]; dw[5] = dn_row[c0 + 4];

        const float cx[4] = {ctr.x, ctr.y, ctr.z, ctr.w};
#pragma unroll
        for (int e = 0; e < 4; ++e) {
            const float x = cx[e];
            const float m = fminf(fminf(fabsf(up[e] - x), fabsf(up[e + 2] - x)),
                                  fminf(fabsf(dw[e] - x), fabsf(dw[e + 2] - x)));
            adj[e] = (m <= thr);
        }
    } else {
        const bool rm = (r >= 1), rp = (r <= PM - 2);
        const float4 ctr = *reinterpret_cast<const float4*>(&g_dnT[rowb + c0]);
        const float* up_row = &g_dnT[(uint32_t)(rm ? r - 1 : r) << 11];
        const float* dn_row = &g_dnT[(uint32_t)(rp ? r + 1 : r) << 11];
        const int cl = (c0 > 0) ? c0 - 1 : 0;
        const int cr = (c0 + 4 < PN) ? c0 + 4 : PN - 1;

        float up[6], dw[6];
        const float4 u4 = *reinterpret_cast<const float4*>(up_row + c0);
        const float4 d4 = *reinterpret_cast<const float4*>(dn_row + c0);
        up[1] = u4.x; up[2] = u4.y; up[3] = u4.z; up[4] = u4.w;
        dw[1] = d4.x; dw[2] = d4.y; dw[3] = d4.z; dw[4] = d4.w;
        up[0] = up_row[cl]; up[5] = up_row[cr];
        dw[0] = dn_row[cl]; dw[5] = dn_row[cr];

        const float cx[4] = {ctr.x, ctr.y, ctr.z, ctr.w};
#pragma unroll
        for (int e = 0; e < 4; ++e) {
            const int c = c0 + e;
            const bool cm = (c >= 1), cp = (c <= PN - 2);
            const float x = cx[e];
            bool a = false;
            a |= (cm && rm)             && (fabsf(up[e]     - x) <= thr);
            a |= (cm && cp && rm && rp) && (fabsf(up[e + 2] - x) <= thr);
            a |= (cm && rp)             && (fabsf(dw[e]     - x) <= thr);
            a |= (cp && rp)             && (fabsf(dw[e + 2] - x) <= thr);
            adj[e] = a;
        }
    }

    // write adjacency as float (dropout applied below by overwrite-to-0)
    *reinterpret_cast<float4*>(&out[rowb + c0]) =
        make_float4(adj[0] ? 1.0f : 0.0f, adj[1] ? 1.0f : 0.0f,
                    adj[2] ? 1.0f : 0.0f, adj[3] ? 1.0f : 0.0f);

    // compact survivor indices into smem: one shared atomic per warp.
    __syncthreads();                       // sh_cnt init visible
    const unsigned lane_lt = (1u << tx) - 1u;
    unsigned mk[4];
#pragma unroll
    for (int e = 0; e < 4; ++e) mk[e] = __ballot_sync(0xffffffffu, adj[e]);
    const int tot = __popc(mk[0]) + __popc(mk[1]) + __popc(mk[2]) + __popc(mk[3]);

    unsigned base = 0;
    if (tx == 0 && tot > 0) base = atomicAdd(&sh_cnt, (unsigned)tot);
    base = __shfl_sync(0xffffffffu, base, 0);

    unsigned off = 0;
#pragma unroll
    for (int e = 0; e < 4; ++e) {
        if (adj[e])
            s_list[base + off + __popc(mk[e] & lane_lt)] =
                rowb + (uint32_t)(c0 + e);
        off += __popc(mk[e]);
    }
    __syncthreads();

    // dense dropout cipher over the ~15 survivors in this block.
    const unsigned n = sh_cnt;
    for (unsigned k = (unsigned)tid; k < n; k += 256u) {
        const uint32_t t = s_list[k];
        const uint32_t bd = tf_bits32(kd0, kd1, 0u, t);
        if (bd & 0x80000000u) out[t] = 0.0f;   // u01(bd) >= 0.5 -> dropped
    }
}

extern "C" void kernel_launch(void* const* d_in, const int* in_sizes, int n_in,
                              void* d_out, int out_size) {
    (void)in_sizes; (void)n_in; (void)out_size;
    const float* dc = (const float*)d_in[0];
    float* out = (float*)d_out;

    // host-side threefry for the key split
    auto rotl_h = [](uint32_t x, int d) { return (x << d) | (x >> (32 - d)); };
    auto tf_h = [&](uint32_t k0, uint32_t k1, uint32_t c0, uint32_t c1,
                    uint32_t& o0, uint32_t& o1) {
        uint32_t ks2 = k0 ^ k1 ^ 0x1BD11BDAu;
        uint32_t x0 = c0 + k0, x1 = c1 + k1;
        const int ra[4] = {13, 15, 26, 6}, rb[4] = {17, 29, 16, 24};
        for (int g = 0; g < 5; ++g) {
            const int* rr = (g & 1) ? rb : ra;
            for (int q = 0; q < 4; ++q) { x0 += x1; x1 = rotl_h(x1, rr[q]); x1 ^= x0; }
            switch (g) {
                case 0: x0 += k1;  x1 += ks2 + 1u; break;
                case 1: x0 += ks2; x1 += k0 + 2u;  break;
                case 2: x0 += k0;  x1 += k1 + 3u;  break;
                case 3: x0 += k1;  x1 += ks2 + 4u; break;
                case 4: x0 += ks2; x1 += k0 + 5u;  break;
            }
        }
        o0 = x0; o1 = x1;
    };

    uint32_t kn0, kn1, kd0, kd1;
    tf_h(0u, 1u, 0u, 0u, kn0, kn1);   // k_noise
    tf_h(0u, 1u, 0u, 1u, kd0, kd1);   // k_drop

    pool_noise_kernel<<<dim3(32, 64), dim3(32, 8)>>>(dc, kn0, kn1);
    graph_kernel<<<dim3(16, 256), dim3(32, 8)>>>(out, kd0, kd1);
}